// round 8
// baseline (speedup 1.0000x reference)
#include <cuda_runtime.h>
#include <cuda_fp16.h>
#include <cstdint>

#define Bc 8
#define Lc 1024
#define Hc 8
#define Ec 64
#define QT 128
#define ST 64
#define SH 72      /* smem row stride in halves */
#define C2 0.18033688f   /* 0.125 * log2(e) */
#define ONE2 0x3C003C00u /* half2(1.0, 1.0) */

__device__ __forceinline__ uint32_t smem_u32(const void* p) {
    return (uint32_t)__cvta_generic_to_shared(p);
}
__device__ __forceinline__ float ex2f(float x) {
    float r; asm("ex2.approx.f32 %0, %1;" : "=f"(r) : "f"(x)); return r;
}
__device__ __forceinline__ uint32_t hex2(uint32_t x) {
    uint32_t r; asm("ex2.approx.f16x2 %0, %1;" : "=r"(r) : "r"(x)); return r;
}
__device__ __forceinline__ uint32_t hmul2u(uint32_t a, uint32_t b) {
    uint32_t r; asm("mul.f16x2 %0, %1, %2;" : "=r"(r) : "r"(a), "r"(b)); return r;
}
__device__ __forceinline__ void ldsm4(uint32_t& r0, uint32_t& r1, uint32_t& r2, uint32_t& r3, uint32_t a) {
    asm volatile("ldmatrix.sync.aligned.m8n8.x4.shared.b16 {%0,%1,%2,%3}, [%4];"
        : "=r"(r0), "=r"(r1), "=r"(r2), "=r"(r3) : "r"(a));
}
__device__ __forceinline__ void ldsm4t(uint32_t& r0, uint32_t& r1, uint32_t& r2, uint32_t& r3, uint32_t a) {
    asm volatile("ldmatrix.sync.aligned.m8n8.x4.trans.shared.b16 {%0,%1,%2,%3}, [%4];"
        : "=r"(r0), "=r"(r1), "=r"(r2), "=r"(r3) : "r"(a));
}
__device__ __forceinline__ void mma16(float* d, const uint32_t* a, uint32_t b0, uint32_t b1) {
    asm volatile("mma.sync.aligned.m16n8k16.row.col.f32.f16.f16.f32 "
        "{%0,%1,%2,%3}, {%4,%5,%6,%7}, {%8,%9}, {%0,%1,%2,%3};"
        : "+f"(d[0]), "+f"(d[1]), "+f"(d[2]), "+f"(d[3])
        : "r"(a[0]), "r"(a[1]), "r"(a[2]), "r"(a[3]), "r"(b0), "r"(b1));
}
__device__ __forceinline__ uint32_t packh2(float x, float y) {
    __half2 h = __floats2half2_rn(x, y);
    return *(uint32_t*)&h;
}

__global__ __launch_bounds__(256, 3) void fftcca_h16v5(
    const float* __restrict__ Q, const float* __restrict__ K,
    const float* __restrict__ V, const float* __restrict__ QD,
    const float* __restrict__ KD, const float* __restrict__ VD,
    const int* __restrict__ histp, float* __restrict__ O)
{
    extern __shared__ __align__(16) char smraw[];
    __half* sq  = (__half*)smraw;                 // [128][72] q_eff
    __half* sKV = sq + QT * SH;                   // [2 stages][K|V][64][72]
    float* sdiag = (float*)(sKV + 4 * ST * SH);   // [128]

    const int hist = __ldg(histp);
    const int b = blockIdx.z, h = blockIdx.y;
    const int jt = (int)(gridDim.x - 1u - blockIdx.x);   // longest tiles first
    const int l0 = jt * QT;
    const int tid = threadIdx.x;
    const int w = tid >> 5, lane = tid & 31, gid = lane >> 2, tig = lane & 3;
    const int g8 = lane >> 3, rl = lane & 7;
    const uint32_t c2x2 = packh2(C2, C2);
    const int bh64 = ((b * Lc) * Hc + h) << 6;

    // ---- stage Q (row-select Q vs QD, cvt fp16) ----
    #pragma unroll
    for (int i = 0; i < 8; ++i) {
        int gi = tid + 256 * i;
        int r = gi >> 4, c4 = (gi & 15) << 2;
        int l = l0 + r;
        const float* src = (l < hist) ? Q : QD;
        float4 v = *(const float4*)(src + bh64 + (l << 9) + c4);
        uint2 pk; pk.x = packh2(v.x, v.y); pk.y = packh2(v.z, v.w);
        *(uint2*)(sq + r * SH + c4) = pk;
    }

    // ---- raw diagonal scores (fp32 from global, 2 threads/row) ----
    {
        int r = tid >> 1, part = tid & 1;
        int l = l0 + r;
        float s = 0.f;
        if (l >= hist) {
            int base = bh64 + (l << 9);
            const float* qr = QD + base + part * 32;
            const float* kr = KD + base + part * 32;
            #pragma unroll
            for (int e = 0; e < 32; e += 4) {
                float4 q4 = *(const float4*)(qr + e);
                float4 k4 = *(const float4*)(kr + e);
                s += q4.x * k4.x + q4.y * k4.y + q4.z * k4.z + q4.w * k4.w;
            }
        }
        s += __shfl_xor_sync(0xffffffffu, s, 1);
        if (part == 0) sdiag[r] = s;
    }
    __syncthreads();

    // ---- preload Q A-fragments (tile-invariant) ----
    uint32_t qa[4][4];
    #pragma unroll
    for (int kb = 0; kb < 4; ++kb) {
        int row = w * 16 + (g8 & 1) * 8 + rl;
        int col = kb * 16 + (g8 >> 1) * 8;
        ldsm4(qa[kb][0], qa[kb][1], qa[kb][2], qa[kb][3], smem_u32(sq + row * SH + col));
    }

    /* acc[0..7]: output dims; acc[8]: ones-column row sums */
    float acc[9][4];
    #pragma unroll
    for (int nb = 0; nb < 9; ++nb)
        #pragma unroll
        for (int q = 0; q < 4; ++q) acc[nb][q] = 0.f;

    const int rowmax = l0 + w * 16 + 15;
    const int dtile = (l0 + w * 16) & ~63;
    const int ntiles = 2 * jt + 2;

    // ---- stage tile 0 into buffer 0 ----
    #pragma unroll
    for (int arr = 0; arr < 2; ++arr) {
        const float* src = arr ? V : K;
        __half* dst = sKV + arr * (ST * SH);
        #pragma unroll
        for (int i = 0; i < 2; ++i) {
            int ch = tid + 256 * i;
            int row = ch >> 3, cc = ch & 7;
            const float* g = src + bh64 + (row << 9) + cc * 8;
            float4 a = *(const float4*)g;
            float4 c = *(const float4*)(g + 4);
            uint4 pk;
            pk.x = packh2(a.x, a.y); pk.y = packh2(a.z, a.w);
            pk.z = packh2(c.x, c.y); pk.w = packh2(c.z, c.w);
            *(uint4*)(dst + row * SH + cc * 8) = pk;
        }
    }
    __syncthreads();

    for (int t = 0; t < ntiles; ++t) {
        const int s0 = t * ST;
        const int cur = t & 1;
        const __half* sK = sKV + cur * (2 * ST * SH);
        const __half* sV = sK + ST * SH;

        // ---- stage tile t+1 into the other buffer ----
        if (t + 1 < ntiles) {
            __half* dB = sKV + (cur ^ 1) * (2 * ST * SH);
            #pragma unroll
            for (int arr = 0; arr < 2; ++arr) {
                const float* src = arr ? V : K;
                __half* dst = dB + arr * (ST * SH);
                #pragma unroll
                for (int i = 0; i < 2; ++i) {
                    int ch = tid + 256 * i;
                    int row = ch >> 3, cc = ch & 7;
                    const float* g = src + bh64 + ((s0 + ST + row) << 9) + cc * 8;
                    float4 a = *(const float4*)g;
                    float4 c = *(const float4*)(g + 4);
                    uint4 pk;
                    pk.x = packh2(a.x, a.y); pk.y = packh2(a.z, a.w);
                    pk.z = packh2(c.x, c.y); pk.w = packh2(c.z, c.w);
                    *(uint4*)(dst + row * SH + cc * 8) = pk;
                }
            }
        }

        if (s0 <= rowmax) {
            const bool dmask = (s0 == dtile);
            /* two n32 halves: QK -> softmax -> PV, 16-reg score transient */
            #pragma unroll
            for (int hf = 0; hf < 2; ++hf) {
                float c[4][4];
                #pragma unroll
                for (int nb = 0; nb < 4; ++nb)
                    #pragma unroll
                    for (int q = 0; q < 4; ++q) c[nb][q] = 0.f;

                /* QK^T: m16 x n32 x k64 */
                #pragma unroll
                for (int kb = 0; kb < 4; ++kb) {
                    #pragma unroll
                    for (int j = 0; j < 2; ++j) {
                        int row = hf * 32 + 16 * j + (g8 & 1) * 8 + rl;
                        int col = kb * 16 + (g8 >> 1) * 8;
                        uint32_t r0, r1, r2, r3;
                        ldsm4(r0, r1, r2, r3, smem_u32(sK + row * SH + col));
                        mma16(c[2 * j],     qa[kb], r0, r2);
                        mma16(c[2 * j + 1], qa[kb], r1, r3);
                    }
                }

                /* diag replace + causal mask (diagonal tile only) */
                if (dmask) {
                    #pragma unroll
                    for (int st = 0; st < 2; ++st) {
                        int lr = w * 16 + st * 8 + gid;
                        int l = l0 + lr;
                        float ds = sdiag[lr];
                        #pragma unroll
                        for (int nb = 0; nb < 4; ++nb)
                            #pragma unroll
                            for (int cc = 0; cc < 2; ++cc) {
                                int sg = s0 + hf * 32 + nb * 8 + 2 * tig + cc;
                                float v = c[nb][2 * st + cc];
                                if (sg == l && l >= hist) v = ds;
                                if (sg > l) v = -1e30f;
                                c[nb][2 * st + cc] = v;
                            }
                    }
                }

                /* fused fp16 softmax + P·V over this half's 32 s-rows */
                #pragma unroll
                for (int kbl = 0; kbl < 2; ++kbl) {
                    uint32_t pa[4];
                    pa[0] = hex2(hmul2u(packh2(c[2 * kbl][0],     c[2 * kbl][1]),     c2x2));
                    pa[1] = hex2(hmul2u(packh2(c[2 * kbl][2],     c[2 * kbl][3]),     c2x2));
                    pa[2] = hex2(hmul2u(packh2(c[2 * kbl + 1][0], c[2 * kbl + 1][1]), c2x2));
                    pa[3] = hex2(hmul2u(packh2(c[2 * kbl + 1][2], c[2 * kbl + 1][3]), c2x2));
                    int srow = hf * 32 + kbl * 16 + (g8 & 1) * 8 + rl;
                    #pragma unroll
                    for (int j = 0; j < 4; ++j) {
                        int dcol = 16 * j + (g8 >> 1) * 8;
                        uint32_t r0, r1, r2, r3;
                        ldsm4t(r0, r1, r2, r3, smem_u32(sV + srow * SH + dcol));
                        mma16(acc[2 * j],     pa, r0, r1);
                        mma16(acc[2 * j + 1], pa, r2, r3);
                    }
                    mma16(acc[8], pa, ONE2, ONE2);
                }
            }
        }
        __syncthreads();
    }

    // ---- epilogue: normalize, delta correction ----
    #pragma unroll
    for (int st = 0; st < 2; ++st) {
        int lr = w * 16 + st * 8 + gid;
        int l = l0 + lr;
        float inv = 1.f / acc[8][2 * st];
        bool tail = (l >= hist);
        float pd = 0.f;
        if (tail) pd = ex2f(sdiag[lr] * C2) * inv;
        #pragma unroll
        for (int nb = 0; nb < 8; ++nb) {
            int d = nb * 8 + 2 * tig;
            int base = bh64 + (l << 9) + d;
            float o0 = acc[nb][2 * st] * inv;
            float o1 = acc[nb][2 * st + 1] * inv;
            if (tail) {
                float2 v2  = *(const float2*)(V  + base);
                float2 vd2 = *(const float2*)(VD + base);
                o0 += pd * (vd2.x - v2.x);
                o1 += pd * (vd2.y - v2.y);
            }
            *(float2*)(O + base) = make_float2(o0, o1);
        }
    }
}

extern "C" void kernel_launch(void* const* d_in, const int* in_sizes, int n_in,
                              void* d_out, int out_size) {
    const float* Q  = (const float*)d_in[0];
    const float* K  = (const float*)d_in[1];
    const float* V  = (const float*)d_in[2];
    const float* QD = (const float*)d_in[3];
    const float* KD = (const float*)d_in[4];
    const float* VD = (const float*)d_in[5];
    const int* histp = (const int*)d_in[(n_in >= 8) ? 7 : (n_in - 1)];

    size_t smem_bytes = (size_t)(QT * SH + 4 * ST * SH) * sizeof(__half) + 128 * sizeof(float);
    cudaFuncSetAttribute(fftcca_h16v5,
                         cudaFuncAttributeMaxDynamicSharedMemorySize, (int)smem_bytes);

    dim3 grid(Lc / QT, Hc, Bc);
    fftcca_h16v5<<<grid, 256, smem_bytes>>>(Q, K, V, QD, KD, VD, histp, (float*)d_out);
}

// round 9
// speedup vs baseline: 1.1755x; 1.1755x over previous
#include <cuda_runtime.h>
#include <cuda_fp16.h>
#include <cstdint>

#define Bc 8
#define Lc 1024
#define Hc 8
#define Ec 64
#define QT 128
#define ST 128     /* s-tile: two independent 64-col halves per barrier window */
#define SH 72      /* smem row stride in halves */
#define C2 0.18033688f   /* 0.125 * log2(e) */
#define ONE2 0x3C003C00u /* half2(1.0, 1.0) */

__device__ __forceinline__ uint32_t smem_u32(const void* p) {
    return (uint32_t)__cvta_generic_to_shared(p);
}
__device__ __forceinline__ float ex2f(float x) {
    float r; asm("ex2.approx.f32 %0, %1;" : "=f"(r) : "f"(x)); return r;
}
__device__ __forceinline__ uint32_t hex2(uint32_t x) {
    uint32_t r; asm("ex2.approx.f16x2 %0, %1;" : "=r"(r) : "r"(x)); return r;
}
__device__ __forceinline__ uint32_t hmul2u(uint32_t a, uint32_t b) {
    uint32_t r; asm("mul.f16x2 %0, %1, %2;" : "=r"(r) : "r"(a), "r"(b)); return r;
}
__device__ __forceinline__ void ldsm4(uint32_t& r0, uint32_t& r1, uint32_t& r2, uint32_t& r3, uint32_t a) {
    asm volatile("ldmatrix.sync.aligned.m8n8.x4.shared.b16 {%0,%1,%2,%3}, [%4];"
        : "=r"(r0), "=r"(r1), "=r"(r2), "=r"(r3) : "r"(a));
}
__device__ __forceinline__ void ldsm4t(uint32_t& r0, uint32_t& r1, uint32_t& r2, uint32_t& r3, uint32_t a) {
    asm volatile("ldmatrix.sync.aligned.m8n8.x4.trans.shared.b16 {%0,%1,%2,%3}, [%4];"
        : "=r"(r0), "=r"(r1), "=r"(r2), "=r"(r3) : "r"(a));
}
__device__ __forceinline__ void mma16(float* d, const uint32_t* a, uint32_t b0, uint32_t b1) {
    asm volatile("mma.sync.aligned.m16n8k16.row.col.f32.f16.f16.f32 "
        "{%0,%1,%2,%3}, {%4,%5,%6,%7}, {%8,%9}, {%0,%1,%2,%3};"
        : "+f"(d[0]), "+f"(d[1]), "+f"(d[2]), "+f"(d[3])
        : "r"(a[0]), "r"(a[1]), "r"(a[2]), "r"(a[3]), "r"(b0), "r"(b1));
}
__device__ __forceinline__ uint32_t packh2(float x, float y) {
    __half2 h = __floats2half2_rn(x, y);
    return *(uint32_t*)&h;
}

__global__ __launch_bounds__(256, 2) void fftcca_h16v6(
    const float* __restrict__ Q, const float* __restrict__ K,
    const float* __restrict__ V, const float* __restrict__ QD,
    const float* __restrict__ KD, const float* __restrict__ VD,
    const int* __restrict__ histp, float* __restrict__ O)
{
    extern __shared__ __align__(16) char smraw[];
    __half* sq  = (__half*)smraw;                 // [128][72] q_eff
    __half* sKV = sq + QT * SH;                   // [2 stages][K|V][128][72]
    float* sdiag = (float*)(sKV + 4 * ST * SH);   // [128]

    const int hist = __ldg(histp);
    const int b = blockIdx.z, h = blockIdx.y;
    const int jt = (int)(gridDim.x - 1u - blockIdx.x);   // longest tiles first
    const int l0 = jt * QT;
    const int tid = threadIdx.x;
    const int w = tid >> 5, lane = tid & 31, gid = lane >> 2, tig = lane & 3;
    const int g8 = lane >> 3, rl = lane & 7;
    const uint32_t c2x2 = packh2(C2, C2);
    const int bh64 = ((b * Lc) * Hc + h) << 6;

    // ---- stage Q (row-select Q vs QD, cvt fp16) ----
    #pragma unroll
    for (int i = 0; i < 8; ++i) {
        int gi = tid + 256 * i;
        int r = gi >> 4, c4 = (gi & 15) << 2;
        int l = l0 + r;
        const float* src = (l < hist) ? Q : QD;
        float4 v = *(const float4*)(src + bh64 + (l << 9) + c4);
        uint2 pk; pk.x = packh2(v.x, v.y); pk.y = packh2(v.z, v.w);
        *(uint2*)(sq + r * SH + c4) = pk;
    }

    // ---- raw diagonal scores (fp32 from global, 2 threads/row) ----
    {
        int r = tid >> 1, part = tid & 1;
        int l = l0 + r;
        float s = 0.f;
        if (l >= hist) {
            int base = bh64 + (l << 9);
            const float* qr = QD + base + part * 32;
            const float* kr = KD + base + part * 32;
            #pragma unroll
            for (int e = 0; e < 32; e += 4) {
                float4 q4 = *(const float4*)(qr + e);
                float4 k4 = *(const float4*)(kr + e);
                s += q4.x * k4.x + q4.y * k4.y + q4.z * k4.z + q4.w * k4.w;
            }
        }
        s += __shfl_xor_sync(0xffffffffu, s, 1);
        if (part == 0) sdiag[r] = s;
    }
    __syncthreads();

    // ---- preload Q A-fragments (tile-invariant) ----
    uint32_t qa[4][4];
    #pragma unroll
    for (int kb = 0; kb < 4; ++kb) {
        int row = w * 16 + (g8 & 1) * 8 + rl;
        int col = kb * 16 + (g8 >> 1) * 8;
        ldsm4(qa[kb][0], qa[kb][1], qa[kb][2], qa[kb][3], smem_u32(sq + row * SH + col));
    }

    /* acc[0..7]: output dims; acc[8]: ones-column row sums */
    float acc[9][4];
    #pragma unroll
    for (int nb = 0; nb < 9; ++nb)
        #pragma unroll
        for (int q = 0; q < 4; ++q) acc[nb][q] = 0.f;

    const int rowmax = l0 + w * 16 + 15;
    const int dtile = (l0 + w * 16) & ~63;
    const int ntiles = jt + 1;

    // ---- stage tile 0 into buffer 0 ----
    #pragma unroll
    for (int arr = 0; arr < 2; ++arr) {
        const float* src = arr ? V : K;
        __half* dst = sKV + arr * (ST * SH);
        #pragma unroll
        for (int i = 0; i < 4; ++i) {
            int ch = tid + 256 * i;            /* 1024 chunks of 16B */
            int row = ch >> 3, cc = ch & 7;
            const float* g = src + bh64 + (row << 9) + cc * 8;
            float4 a = *(const float4*)g;
            float4 c = *(const float4*)(g + 4);
            uint4 pk;
            pk.x = packh2(a.x, a.y); pk.y = packh2(a.z, a.w);
            pk.z = packh2(c.x, c.y); pk.w = packh2(c.z, c.w);
            *(uint4*)(dst + row * SH + cc * 8) = pk;
        }
    }
    __syncthreads();

    for (int t = 0; t < ntiles; ++t) {
        const int s0 = t * ST;
        const int cur = t & 1;
        const __half* sK = sKV + cur * (2 * ST * SH);
        const __half* sV = sK + ST * SH;

        // ---- stage tile t+1 into the other buffer ----
        if (t + 1 < ntiles) {
            __half* dB = sKV + (cur ^ 1) * (2 * ST * SH);
            #pragma unroll
            for (int arr = 0; arr < 2; ++arr) {
                const float* src = arr ? V : K;
                __half* dst = dB + arr * (ST * SH);
                #pragma unroll
                for (int i = 0; i < 4; ++i) {
                    int ch = tid + 256 * i;
                    int row = ch >> 3, cc = ch & 7;
                    const float* g = src + bh64 + ((s0 + ST + row) << 9) + cc * 8;
                    float4 a = *(const float4*)g;
                    float4 c = *(const float4*)(g + 4);
                    uint4 pk;
                    pk.x = packh2(a.x, a.y); pk.y = packh2(a.z, a.w);
                    pk.z = packh2(c.x, c.y); pk.w = packh2(c.z, c.w);
                    *(uint4*)(dst + row * SH + cc * 8) = pk;
                }
            }
        }

        /* ---- two independent 64-col halves in one barrier window ---- */
        #pragma unroll
        for (int hf = 0; hf < 2; ++hf) {
            const int sb = s0 + hf * 64;              /* half's s-block base */
            if (sb > rowmax) continue;                /* 64-col skip granularity */
            const __half* sKh = sK + hf * 64 * SH;
            const __half* sVh = sV + hf * 64 * SH;

            float c[8][4];
            #pragma unroll
            for (int nb = 0; nb < 8; ++nb)
                #pragma unroll
                for (int q = 0; q < 4; ++q) c[nb][q] = 0.f;

            /* QK^T: m16 x n64 x k64 */
            #pragma unroll
            for (int kb = 0; kb < 4; ++kb) {
                #pragma unroll
                for (int j = 0; j < 4; ++j) {
                    int row = 16 * j + (g8 & 1) * 8 + rl;
                    int col = kb * 16 + (g8 >> 1) * 8;
                    uint32_t r0, r1, r2, r3;
                    ldsm4(r0, r1, r2, r3, smem_u32(sKh + row * SH + col));
                    mma16(c[2 * j],     qa[kb], r0, r2);
                    mma16(c[2 * j + 1], qa[kb], r1, r3);
                }
            }

            /* diag replace + causal mask (this warp's diagonal half only) */
            if (sb == dtile) {
                #pragma unroll
                for (int st = 0; st < 2; ++st) {
                    int lr = w * 16 + st * 8 + gid;
                    int l = l0 + lr;
                    float ds = sdiag[lr];
                    #pragma unroll
                    for (int nb = 0; nb < 8; ++nb)
                        #pragma unroll
                        for (int cc = 0; cc < 2; ++cc) {
                            int sg = sb + nb * 8 + 2 * tig + cc;
                            float v = c[nb][2 * st + cc];
                            if (sg == l && l >= hist) v = ds;
                            if (sg > l) v = -1e30f;
                            c[nb][2 * st + cc] = v;
                        }
                }
            }

            /* fused fp16 softmax + P·V + ones-column row sums */
            #pragma unroll
            for (int kb = 0; kb < 4; ++kb) {
                uint32_t pa[4];
                pa[0] = hex2(hmul2u(packh2(c[2 * kb][0],     c[2 * kb][1]),     c2x2));
                pa[1] = hex2(hmul2u(packh2(c[2 * kb][2],     c[2 * kb][3]),     c2x2));
                pa[2] = hex2(hmul2u(packh2(c[2 * kb + 1][0], c[2 * kb + 1][1]), c2x2));
                pa[3] = hex2(hmul2u(packh2(c[2 * kb + 1][2], c[2 * kb + 1][3]), c2x2));
                int srow = kb * 16 + (g8 & 1) * 8 + rl;
                #pragma unroll
                for (int j = 0; j < 4; ++j) {
                    int dcol = 16 * j + (g8 >> 1) * 8;
                    uint32_t r0, r1, r2, r3;
                    ldsm4t(r0, r1, r2, r3, smem_u32(sVh + srow * SH + dcol));
                    mma16(acc[2 * j],     pa, r0, r1);
                    mma16(acc[2 * j + 1], pa, r2, r3);
                }
                mma16(acc[8], pa, ONE2, ONE2);
            }
        }
        __syncthreads();
    }

    // ---- epilogue: normalize, delta correction ----
    #pragma unroll
    for (int st = 0; st < 2; ++st) {
        int lr = w * 16 + st * 8 + gid;
        int l = l0 + lr;
        float inv = 1.f / acc[8][2 * st];
        bool tail = (l >= hist);
        float pd = 0.f;
        if (tail) pd = ex2f(sdiag[lr] * C2) * inv;
        #pragma unroll
        for (int nb = 0; nb < 8; ++nb) {
            int d = nb * 8 + 2 * tig;
            int base = bh64 + (l << 9) + d;
            float o0 = acc[nb][2 * st] * inv;
            float o1 = acc[nb][2 * st + 1] * inv;
            if (tail) {
                float2 v2  = *(const float2*)(V  + base);
                float2 vd2 = *(const float2*)(VD + base);
                o0 += pd * (vd2.x - v2.x);
                o1 += pd * (vd2.y - v2.y);
            }
            *(float2*)(O + base) = make_float2(o0, o1);
        }
    }
}

extern "C" void kernel_launch(void* const* d_in, const int* in_sizes, int n_in,
                              void* d_out, int out_size) {
    const float* Q  = (const float*)d_in[0];
    const float* K  = (const float*)d_in[1];
    const float* V  = (const float*)d_in[2];
    const float* QD = (const float*)d_in[3];
    const float* KD = (const float*)d_in[4];
    const float* VD = (const float*)d_in[5];
    const int* histp = (const int*)d_in[(n_in >= 8) ? 7 : (n_in - 1)];

    size_t smem_bytes = (size_t)(QT * SH + 4 * ST * SH) * sizeof(__half) + 128 * sizeof(float);
    cudaFuncSetAttribute(fftcca_h16v6,
                         cudaFuncAttributeMaxDynamicSharedMemorySize, (int)smem_bytes);

    dim3 grid(Lc / QT, Hc, Bc);
    fftcca_h16v6<<<grid, 256, smem_bytes>>>(Q, K, V, QD, KD, VD, histp, (float*)d_out);
}